// round 15
// baseline (speedup 1.0000x reference)
#include <cuda_runtime.h>

#define BATCH    4
#define NPTS     4096
#define THREADS  256
#define QCHUNKS  (NPTS / THREADS)        // 16
#define GRID_T   (QCHUNKS * 2 * BATCH)   // 128 blocks
#define NBKT     1024
#define U0       (-12.0f)                // u = x+y+z ~ N(0,3); +-12 = 6.9 sigma
#define UW       (24.0f / NBKT)
#define INV_UW   (NBKT / 24.0f)

// sst: 4096 float2 (s=x+y, t=x-y) bucket-ordered   32768 B
// szs: 4096 float  (z)                              16384 B
// off: 1025 u32 bucket start offsets                 4100 B
// cnt: 1024 u32 histogram / scatter cursors          4096 B
// red: reduction scratch                               32 B
#define SMEM_BYTES (32768 + 16384 + 1025 * 4 + 1024 * 4 + 64)

__device__ float    g_acc;   // zero-init; last block resets after reading
__device__ unsigned g_cnt;

__global__ __launch_bounds__(THREADS)
void chamfer_bucket_kernel(const float* __restrict__ pred,
                           const float* __restrict__ gt,
                           float* __restrict__ out) {
    extern __shared__ char smem[];
    float2*   sst = reinterpret_cast<float2*>(smem);
    float*    szs = reinterpret_cast<float*>(smem + 32768);
    unsigned* off = reinterpret_cast<unsigned*>(smem + 32768 + 16384);
    unsigned* cnt = off + 1025;
    float*    red = reinterpret_cast<float*>(cnt + 1024);

    const int tid    = threadIdx.x;
    const int qchunk = blockIdx.x;       // 0..15
    const int dir    = blockIdx.y;       // 0: pred->gt, 1: gt->pred
    const int b      = blockIdx.z;       // 0..3
    const int lane   = tid & 31;
    const int wid    = tid >> 5;

    const float* src = (dir ? gt : pred) + (size_t)b * NPTS * 3;  // queries
    const float* tgt = (dir ? pred : gt) + (size_t)b * NPTS * 3;  // targets

    // ---- Phase 1: bucket the target cloud by u = x+y+z ----
    for (int i = tid; i < NBKT; i += THREADS) cnt[i] = 0u;
    __syncthreads();

    #pragma unroll 4
    for (int k = 0; k < NPTS / THREADS; k++) {
        const int p = k * THREADS + tid;
        const float x = tgt[p * 3], y = tgt[p * 3 + 1], z = tgt[p * 3 + 2];
        int bk = (int)((x + y + z - U0) * INV_UW);
        bk = min(max(bk, 0), NBKT - 1);
        atomicAdd(&cnt[bk], 1u);
    }
    __syncthreads();

    // exclusive prefix over 1024 counters (4 per thread)
    {
        __shared__ unsigned wtot[8], wbase[8];
        const unsigned c0 = cnt[tid * 4],     c1 = cnt[tid * 4 + 1];
        const unsigned c2 = cnt[tid * 4 + 2], c3 = cnt[tid * 4 + 3];
        const unsigned tsum = c0 + c1 + c2 + c3;
        unsigned scan = tsum;
        #pragma unroll
        for (int o = 1; o < 32; o <<= 1) {
            const unsigned n = __shfl_up_sync(0xffffffffu, scan, o);
            if (lane >= o) scan += n;
        }
        if (lane == 31) wtot[wid] = scan;
        __syncthreads();
        if (tid == 0) {
            unsigned v = 0;
            for (int w = 0; w < 8; w++) { wbase[w] = v; v += wtot[w]; }
        }
        __syncthreads();
        const unsigned base = wbase[wid] + scan - tsum;
        off[tid * 4]     = base;
        off[tid * 4 + 1] = base + c0;
        off[tid * 4 + 2] = base + c0 + c1;
        off[tid * 4 + 3] = base + c0 + c1 + c2;
        if (tid == THREADS - 1) off[NBKT] = NPTS;
    }
    __syncthreads();
    for (int i = tid; i < NBKT; i += THREADS) cnt[i] = off[i];  // scatter cursors
    __syncthreads();

    #pragma unroll 4
    for (int k = 0; k < NPTS / THREADS; k++) {
        const int p = k * THREADS + tid;
        const float x = tgt[p * 3], y = tgt[p * 3 + 1], z = tgt[p * 3 + 2];
        int bk = (int)((x + y + z - U0) * INV_UW);
        bk = min(max(bk, 0), NBKT - 1);
        const unsigned pos = atomicAdd(&cnt[bk], 1u);
        sst[pos] = make_float2(x + y, x - y);
        szs[pos] = z;
    }
    __syncthreads();

    // ---- Phase 2: per-lane exact NN, flat counted loops (no SHFL) ----
    const int qi = qchunk * THREADS + tid;
    const float qx = src[qi * 3], qy = src[qi * 3 + 1], qz = src[qi * 3 + 2];
    const float qs = qx + qy, qt = qx - qy;
    const float qu = qs + qz;
    int bq = (int)((qu - U0) * INV_UW);
    bq = min(max(bq, 0), NBKT - 1);

    // (a) upper bound: 64 contiguous candidates centered on own bucket start
    float cur = 3.4e38f;
    {
        int lo = min(max((int)off[bq] - 32, 0), NPTS - 64);
        #pragma unroll 8
        for (int k = 0; k < 64; k++) {
            const float2 st = sst[lo + k];
            const float d = fmaxf(fabsf(qs - st.x), fabsf(qt - st.y))
                          + fabsf(qz - szs[lo + k]);
            cur = fminf(cur, d);
        }
    }

    // (b) exact window: every candidate with |u - qu| <= cur (d >= |du|)
    float best = cur;
    {
        int blo = (int)((qu - cur - U0) * INV_UW);
        int bhi = (int)((qu + cur - U0) * INV_UW);
        blo = min(max(blo, 0), NBKT - 1);
        bhi = min(max(bhi, 0), NBKT - 1);
        const unsigned wlo = off[blo], whi = off[bhi + 1];
        #pragma unroll 4
        for (unsigned i = wlo; i < whi; i++) {
            const float2 st = sst[i];
            const float d = fmaxf(fabsf(qs - st.x), fabsf(qt - st.y))
                          + fabsf(qz - szs[i]);
            best = fminf(best, d);
        }
    }

    // ---- Phase 3: block sum -> global atomicAdd -> last block finalizes ----
    float sum = best;
    #pragma unroll
    for (int o = 16; o; o >>= 1)
        sum += __shfl_xor_sync(0xffffffffu, sum, o);
    if (lane == 0) red[wid] = sum;
    __syncthreads();
    if (tid == 0) {
        float v = 0.0f;
        #pragma unroll
        for (int w = 0; w < 8; w++) v += red[w];
        atomicAdd(&g_acc, v);
        __threadfence();
        const unsigned ticket = atomicAdd(&g_cnt, 1u);
        if (ticket == GRID_T - 1) {
            const float total = atomicAdd(&g_acc, 0.0f);   // coherent read
            out[0] = total * (1.0f / ((float)BATCH * (float)NPTS));
            __threadfence();
            g_acc = 0.0f;                                  // reset for replay
            g_cnt = 0u;
        }
    }
}

extern "C" void kernel_launch(void* const* d_in, const int* in_sizes, int n_in,
                              void* d_out, int out_size) {
    const float* pred = (const float*)d_in[0];
    const float* gt   = (const float*)d_in[1];
    float* out = (float*)d_out;
    (void)in_sizes; (void)n_in; (void)out_size;

    cudaFuncSetAttribute(chamfer_bucket_kernel,
                         cudaFuncAttributeMaxDynamicSharedMemorySize,
                         SMEM_BYTES);   // idempotent; set on uncaptured first call

    dim3 grid(QCHUNKS, 2, BATCH);      // 16 x 2 x 4 = 128 blocks, one wave
    chamfer_bucket_kernel<<<grid, THREADS, SMEM_BYTES>>>(pred, gt, out);
}

// round 17
// speedup vs baseline: 1.4100x; 1.4100x over previous
#include <cuda_runtime.h>

#define BATCH    4
#define NPTS     4096
#define THREADS  256
#define QCHUNKS  (NPTS / THREADS)        // 16
#define GRID_T   (QCHUNKS * 2 * BATCH)   // 128 blocks
#define NBKT     1024
#define U0       (-12.0f)                // u = x+y+z ~ N(0,3); +-12 = 6.9 sigma
#define UW       (24.0f / NBKT)
#define INV_UW   (NBKT / 24.0f)

// Layout (16B-aligned first):
// spt : 4096 float4 (s,t,z,u) bucket-ordered    [0,      65536)
// qsr : 256 float4 sorted queries               [65536,  69632)
// off : 1025 u32 bucket start offsets           [69632,  73732)
// cnt : 1024 u32 histogram / scatter cursors    [73732,  77828)
// qud : 256 float query-u                       [77828,  78852)
// red : scratch                                 [78852,  78916)
#define SMEM_BYTES 78916

__device__ float    g_acc;   // zero-init; last block resets after reading
__device__ unsigned g_cnt;

__global__ __launch_bounds__(THREADS)
void chamfer_bucket_kernel(const float* __restrict__ pred,
                           const float* __restrict__ gt,
                           float* __restrict__ out) {
    extern __shared__ char smem[];
    float4*   spt = reinterpret_cast<float4*>(smem);
    float4*   qsr = reinterpret_cast<float4*>(smem + 65536);
    unsigned* off = reinterpret_cast<unsigned*>(smem + 69632);
    unsigned* cnt = reinterpret_cast<unsigned*>(smem + 73732);
    float*    qud = reinterpret_cast<float*>(smem + 77828);
    float*    red = reinterpret_cast<float*>(smem + 78852);

    const int tid    = threadIdx.x;
    const int qchunk = blockIdx.x;       // 0..15
    const int dir    = blockIdx.y;       // 0: pred->gt, 1: gt->pred
    const int b      = blockIdx.z;       // 0..3
    const int lane   = tid & 31;
    const int wid    = tid >> 5;

    const float* src = (dir ? gt : pred) + (size_t)b * NPTS * 3;  // queries
    const float* tgt = (dir ? pred : gt) + (size_t)b * NPTS * 3;  // targets

    // ---- Phase 1: bucket-sort the target cloud by u = x+y+z ----
    for (int i = tid; i < NBKT; i += THREADS) cnt[i] = 0u;
    __syncthreads();

    #pragma unroll 4
    for (int k = 0; k < NPTS / THREADS; k++) {
        const int p = k * THREADS + tid;
        const float x = tgt[p * 3], y = tgt[p * 3 + 1], z = tgt[p * 3 + 2];
        int bk = (int)((x + y + z - U0) * INV_UW);
        bk = min(max(bk, 0), NBKT - 1);
        atomicAdd(&cnt[bk], 1u);
    }
    __syncthreads();

    // exclusive prefix over 1024 counters (4 per thread)
    {
        __shared__ unsigned wtot[8], wbase[8];
        const unsigned c0 = cnt[tid * 4],     c1 = cnt[tid * 4 + 1];
        const unsigned c2 = cnt[tid * 4 + 2], c3 = cnt[tid * 4 + 3];
        const unsigned tsum = c0 + c1 + c2 + c3;
        unsigned scan = tsum;
        #pragma unroll
        for (int o = 1; o < 32; o <<= 1) {
            const unsigned n = __shfl_up_sync(0xffffffffu, scan, o);
            if (lane >= o) scan += n;
        }
        if (lane == 31) wtot[wid] = scan;
        __syncthreads();
        if (tid == 0) {
            unsigned v = 0;
            for (int w = 0; w < 8; w++) { wbase[w] = v; v += wtot[w]; }
        }
        __syncthreads();
        const unsigned base = wbase[wid] + scan - tsum;
        off[tid * 4]     = base;
        off[tid * 4 + 1] = base + c0;
        off[tid * 4 + 2] = base + c0 + c1;
        off[tid * 4 + 3] = base + c0 + c1 + c2;
        if (tid == THREADS - 1) off[NBKT] = NPTS;
    }
    __syncthreads();
    for (int i = tid; i < NBKT; i += THREADS) cnt[i] = off[i];  // scatter cursors
    __syncthreads();

    #pragma unroll 4
    for (int k = 0; k < NPTS / THREADS; k++) {
        const int p = k * THREADS + tid;
        const float x = tgt[p * 3], y = tgt[p * 3 + 1], z = tgt[p * 3 + 2];
        const float u = x + y + z;
        int bk = (int)((u - U0) * INV_UW);
        bk = min(max(bk, 0), NBKT - 1);
        const unsigned pos = atomicAdd(&cnt[bk], 1u);
        spt[pos] = make_float4(x + y, x - y, z, u);
    }

    // ---- Phase 1b: sort this block's 256 queries by u (rank counting) ----
    const int qi = qchunk * THREADS + tid;
    {
        const float x = src[qi * 3], y = src[qi * 3 + 1], z = src[qi * 3 + 2];
        const float u = x + y + z;
        qud[tid] = u;
        __syncthreads();
        int rank = 0;
        #pragma unroll 8
        for (int k = 0; k < THREADS; k++) {
            const float v = qud[k];                 // broadcast read
            rank += (v < u) || (v == u && k < tid);
        }
        qsr[rank] = make_float4(x + y, x - y, z, u);
    }
    __syncthreads();

    // ---- Phase 2: warp-uniform union-window scan, broadcast LDS ----
    const float4 q = qsr[tid];
    const float qs = q.x, qt = q.y, qz = q.z, qu = q.w;

    // (a) upper bound: warp-shared 64-candidate seed region (broadcast)
    float cur = 3.4e38f;
    {
        int bq = (int)((__shfl_sync(0xffffffffu, qu, 16) - U0) * INV_UW);
        bq = min(max(bq, 0), NBKT - 1);
        const int lo = min(max((int)off[bq] - 32, 0), NPTS - 64);
        #pragma unroll 8
        for (int k = 0; k < 64; k++) {
            const float4 f = spt[lo + k];           // broadcast
            const float d = fmaxf(fabsf(qs - f.x), fabsf(qt - f.y))
                          + fabsf(qz - f.z);
            cur = fminf(cur, d);
        }
    }

    // (b) per-lane exact window -> warp union (superset scan stays exact)
    int blo = (int)((qu - cur - U0) * INV_UW);
    int bhi = (int)((qu + cur - U0) * INV_UW);
    blo = min(max(blo, 0), NBKT - 1);
    bhi = min(max(bhi, 0), NBKT - 1);
    unsigned uwlo = off[blo], uwhi = off[bhi + 1];
    #pragma unroll
    for (int o = 16; o; o >>= 1) {
        uwlo = min(uwlo, __shfl_xor_sync(0xffffffffu, uwlo, o));
        uwhi = max(uwhi, __shfl_xor_sync(0xffffffffu, uwhi, o));
    }

    // (c) union scan: warp-uniform bounds, broadcast LDS.128, dual accums
    float b0 = cur, b1 = 3.4e38f;
    unsigned i = uwlo;
    for (; i + 2 <= uwhi; i += 2) {
        const float4 f0 = spt[i];
        const float4 f1 = spt[i + 1];
        const float d0 = fmaxf(fabsf(qs - f0.x), fabsf(qt - f0.y))
                       + fabsf(qz - f0.z);
        const float d1 = fmaxf(fabsf(qs - f1.x), fabsf(qt - f1.y))
                       + fabsf(qz - f1.z);
        b0 = fminf(b0, d0);
        b1 = fminf(b1, d1);
    }
    if (i < uwhi) {
        const float4 f = spt[i];
        b0 = fminf(b0, fmaxf(fabsf(qs - f.x), fabsf(qt - f.y))
                       + fabsf(qz - f.z));
    }
    const float best = fminf(b0, b1);

    // ---- Phase 3: block sum -> global atomicAdd -> last block finalizes ----
    float sum = best;
    #pragma unroll
    for (int o = 16; o; o >>= 1)
        sum += __shfl_xor_sync(0xffffffffu, sum, o);
    if (lane == 0) red[wid] = sum;
    __syncthreads();
    if (tid == 0) {
        float v = 0.0f;
        #pragma unroll
        for (int w = 0; w < 8; w++) v += red[w];
        atomicAdd(&g_acc, v);
        __threadfence();
        const unsigned ticket = atomicAdd(&g_cnt, 1u);
        if (ticket == GRID_T - 1) {
            const float total = atomicAdd(&g_acc, 0.0f);   // coherent read
            out[0] = total * (1.0f / ((float)BATCH * (float)NPTS));
            __threadfence();
            g_acc = 0.0f;                                  // reset for replay
            g_cnt = 0u;
        }
    }
}

extern "C" void kernel_launch(void* const* d_in, const int* in_sizes, int n_in,
                              void* d_out, int out_size) {
    const float* pred = (const float*)d_in[0];
    const float* gt   = (const float*)d_in[1];
    float* out = (float*)d_out;
    (void)in_sizes; (void)n_in; (void)out_size;

    cudaFuncSetAttribute(chamfer_bucket_kernel,
                         cudaFuncAttributeMaxDynamicSharedMemorySize,
                         SMEM_BYTES);   // idempotent; set on uncaptured first call

    dim3 grid(QCHUNKS, 2, BATCH);      // 16 x 2 x 4 = 128 blocks, one wave
    chamfer_bucket_kernel<<<grid, THREADS, SMEM_BYTES>>>(pred, gt, out);
}